// round 10
// baseline (speedup 1.0000x reference)
#include <cuda_runtime.h>
#include <cstdint>

#define EDIM    8
#define NCODES  1024
#define NPAIR   512          // NCODES/2
#define HPAIR   256          // pairs per codebook half
#define SP      32768        // 32*32*32 spatial per batch
#define THREADS 128
#define QPT     4            // queries per thread
#define NVEC    262144
#define MTHREADS 256

typedef unsigned long long ull;

// ---- device scratch (no allocations; self-resetting across graph replays) ----
__device__ float    g_bd[2 * NVEC];    // best dist per (half, query)
__device__ int      g_bi[2 * NVEC];    // best code idx per (half, query)
__device__ float    g_partial[4096];   // per-block loss partials (pass 2)
__device__ int      g_used[NCODES];    // set in pass 2, counted+reset by finalizer
__device__ unsigned g_ticket = 0;      // pass-2 completion ticket

// ---- packed f32x2 helpers (Blackwell FFMA2 path, PTX-only) ----
__device__ __forceinline__ ull pack2(float lo, float hi){
    ull d;
    asm("mov.b64 %0, {%1, %2};" : "=l"(d)
        : "r"(__float_as_uint(lo)), "r"(__float_as_uint(hi)));
    return d;
}
__device__ __forceinline__ ull fma2(ull a, ull b, ull c){
    ull d; asm("fma.rn.f32x2 %0, %1, %2, %3;" : "=l"(d) : "l"(a), "l"(b), "l"(c));
    return d;
}
__device__ __forceinline__ ull mul2(ull a, ull b){
    ull d; asm("mul.rn.f32x2 %0, %1, %2;" : "=l"(d) : "l"(a), "l"(b));
    return d;
}
__device__ __forceinline__ ull add2(ull a, ull b){
    ull d; asm("add.rn.f32x2 %0, %1, %2;" : "=l"(d) : "l"(a), "l"(b));
    return d;
}
union U64F2 { ull u; float2 f; };
__device__ __forceinline__ float2 asf2(ull v){ U64F2 x; x.u = v; return x.f; }

// Bit-exact pair distance: d_pair = fma2(dot2, {-2,-2}, add2(ee2, zz2))
// (this exact op structure reproduces the reference's rounding; do not change)
__device__ __forceinline__ ull pair_dist(const ulonglong2* ep, ull eep,
                                         const ull* zp, ull zzp, ull m2){
    const ulonglong2 e01 = ep[0];
    const ulonglong2 e23 = ep[1];
    const ulonglong2 e45 = ep[2];
    const ulonglong2 e67 = ep[3];
    ull a = mul2(zp[0], e01.x);
    a = fma2(zp[1], e01.y, a);
    a = fma2(zp[2], e23.x, a);
    a = fma2(zp[3], e23.y, a);
    a = fma2(zp[4], e45.x, a);
    a = fma2(zp[5], e45.y, a);
    a = fma2(zp[6], e67.x, a);
    a = fma2(zp[7], e67.y, a);
    return fma2(a, m2, add2(eep, zzp));
}

// ---- pass 1: each CTA = (query chunk, codebook half); store (best_d, best_i) ----
__global__ __launch_bounds__(THREADS, 5) void vq_search(
    const float* __restrict__ z,
    const float* __restrict__ emb)
{
    __shared__ __align__(16) float2 sE[HPAIR * EDIM];  // half codebook, 16KB
    __shared__ __align__(16) float  sEE[HPAIR * 2];    // half norms, 2KB

    const int h     = blockIdx.x & 1;        // codebook half
    const int chunk = blockIdx.x >> 1;       // query chunk
    const int pbase = h * HPAIR;             // first global pair of this half

    // Stage this half's codebook: sE[p*8+c] = (e[2P][c], e[2P+1][c]), P = pbase+p
    for (int i = threadIdx.x; i < HPAIR * EDIM; i += THREADS){
        int p = i >> 3, c = i & 7;
        int P = pbase + p;
        sE[i] = make_float2(emb[(2*P)*EDIM + c], emb[(2*P+1)*EDIM + c]);
    }
    for (int j = threadIdx.x; j < HPAIR * 2; j += THREADS){
        int J = 2 * pbase + j;
        float s = 0.f;
        #pragma unroll
        for (int c = 0; c < EDIM; c++){ float e = emb[J*EDIM + c]; s = fmaf(e, e, s); }
        sEE[j] = s;
    }
    __syncthreads();

    const int part = NVEC / QPT;              // 65536
    const int t = chunk * THREADS + threadIdx.x;

    int nq[QPT];
    ull zp[QPT][EDIM];
    ull zzp[QPT];

    #pragma unroll
    for (int q = 0; q < QPT; q++){
        nq[q] = t + q * part;
        const int b = nq[q] >> 15;
        const int s = nq[q] & (SP - 1);
        const float* zptr = z + (size_t)b * (EDIM * SP) + s;
        float zz = 0.f;
        #pragma unroll
        for (int c = 0; c < EDIM; c++){
            float v = zptr[c * SP];
            zp[q][c] = pack2(v, v);
            zz = fmaf(v, v, zz);
        }
        zzp[q] = pack2(zz, zz);
    }
    const ull m2 = pack2(-2.f, -2.f);

    float best[QPT];
    int   bgp[QPT];                            // winning LOCAL group base pair (even)
    #pragma unroll
    for (int q = 0; q < QPT; q++){ best[q] = 3.4e38f; bgp[q] = 0; }

    // Group of 2 pairs per step; codebook loads amortized over 4 queries.
    for (int p = 0; p < HPAIR; p += 2){
        const ulonglong2* epA = reinterpret_cast<const ulonglong2*>(sE + p * EDIM);
        const ulonglong2* epB = reinterpret_cast<const ulonglong2*>(sE + (p + 1) * EDIM);
        const ulonglong2 eeAB = *reinterpret_cast<const ulonglong2*>(sEE + 2 * p);

        float2 dA0 = asf2(pair_dist(epA, eeAB.x, zp[0], zzp[0], m2));
        float2 dA1 = asf2(pair_dist(epA, eeAB.x, zp[1], zzp[1], m2));
        float2 dA2 = asf2(pair_dist(epA, eeAB.x, zp[2], zzp[2], m2));
        float2 dA3 = asf2(pair_dist(epA, eeAB.x, zp[3], zzp[3], m2));
        float2 dB0 = asf2(pair_dist(epB, eeAB.y, zp[0], zzp[0], m2));
        float2 dB1 = asf2(pair_dist(epB, eeAB.y, zp[1], zzp[1], m2));
        float2 dB2 = asf2(pair_dist(epB, eeAB.y, zp[2], zzp[2], m2));
        float2 dB3 = asf2(pair_dist(epB, eeAB.y, zp[3], zzp[3], m2));

        {
            float gm = fminf(fminf(dA0.x, dA0.y), fminf(dB0.x, dB0.y));
            bool u = gm < best[0]; bgp[0] = u ? p : bgp[0]; best[0] = fminf(best[0], gm);
        }
        {
            float gm = fminf(fminf(dA1.x, dA1.y), fminf(dB1.x, dB1.y));
            bool u = gm < best[1]; bgp[1] = u ? p : bgp[1]; best[1] = fminf(best[1], gm);
        }
        {
            float gm = fminf(fminf(dA2.x, dA2.y), fminf(dB2.x, dB2.y));
            bool u = gm < best[2]; bgp[2] = u ? p : bgp[2]; best[2] = fminf(best[2], gm);
        }
        {
            float gm = fminf(fminf(dA3.x, dA3.y), fminf(dB3.x, dB3.y));
            bool u = gm < best[3]; bgp[3] = u ? p : bgp[3]; best[3] = fminf(best[3], gm);
        }
    }

    // Epilogue: rescan winning 2-pair group (bit-exact), first-occurrence argmin,
    // store (dist, global code idx) for the merge pass.
    #pragma unroll
    for (int q = 0; q < QPT; q++){
        const int gp = bgp[q];
        float bd = 3.4e38f;
        int bi = 0;
        #pragma unroll
        for (int j = 0; j < 2; j++){
            const int p = gp + j;
            const ulonglong2* ep = reinterpret_cast<const ulonglong2*>(sE + p * EDIM);
            const ull eep = *reinterpret_cast<const ull*>(sEE + 2 * p);
            float2 df = asf2(pair_dist(ep, eep, zp[q], zzp[q], m2));
            if (df.x < bd){ bd = df.x; bi = 2*(pbase + p); }
            if (df.y < bd){ bd = df.y; bi = 2*(pbase + p) + 1; }
        }
        g_bd[h * NVEC + nq[q]] = bd;
        g_bi[h * NVEC + nq[q]] = bi;
    }
}

// ---- pass 2: merge halves, gather z_q, write idx, loss (= dist) + unique ----
__global__ __launch_bounds__(MTHREADS) void vq_merge(
    const float* __restrict__ emb,
    float* __restrict__ out,
    int nblocks)
{
    __shared__ float sRed[MTHREADS / 32];
    __shared__ bool  sLast;

    const int n = blockIdx.x * MTHREADS + threadIdx.x;
    const int n_z = NVEC * EDIM;

    float lossLocal = 0.f;
    {
        const float d0 = g_bd[n];
        const float d1 = g_bd[NVEC + n];
        const int   i0 = g_bi[n];
        const int   i1 = g_bi[NVEC + n];
        // strict <: half 0 (lower indices) wins ties -> argmin first-occurrence
        const bool take1 = d1 < d0;
        const float d  = take1 ? d1 : d0;
        const int   bi = take1 ? i1 : i0;

        lossLocal = d;     // sum((e-z)^2) == dist (identical up to ~1e-6 rounding)

        const int b = n >> 15;
        const int s = n & (SP - 1);
        const float4* e4 = reinterpret_cast<const float4*>(emb + (size_t)bi * EDIM);
        const float4 e0 = e4[0];
        const float4 e1 = e4[1];
        float* o = out + (size_t)b * (EDIM * SP) + s;
        o[0 * SP] = e0.x; o[1 * SP] = e0.y; o[2 * SP] = e0.z; o[3 * SP] = e0.w;
        o[4 * SP] = e1.x; o[5 * SP] = e1.y; o[6 * SP] = e1.z; o[7 * SP] = e1.w;

        out[n_z + 2 + n] = (float)bi;
        g_used[bi] = 1;
    }

    // Block-reduce loss -> deterministic per-block partial
    #pragma unroll
    for (int o = 16; o > 0; o >>= 1)
        lossLocal += __shfl_down_sync(0xffffffff, lossLocal, o);
    const int lane = threadIdx.x & 31, w = threadIdx.x >> 5;
    if (lane == 0) sRed[w] = lossLocal;
    __syncthreads();
    if (threadIdx.x == 0){
        float v = 0.f;
        #pragma unroll
        for (int i = 0; i < MTHREADS / 32; i++) v += sRed[i];
        g_partial[blockIdx.x] = v;
        __threadfence();
        unsigned old = atomicAdd(&g_ticket, 1u);
        sLast = (old == (unsigned)(nblocks - 1));
    }
    __syncthreads();

    if (sLast){
        __threadfence();
        int cnt = 0;
        for (int i = threadIdx.x; i < NCODES; i += MTHREADS){
            cnt += (g_used[i] != 0);
            g_used[i] = 0;                      // reset for next replay
        }
        float s = 0.f;
        for (int i = threadIdx.x; i < nblocks; i += MTHREADS) s += g_partial[i];

        #pragma unroll
        for (int o = 16; o > 0; o >>= 1){
            s   += __shfl_down_sync(0xffffffff, s, o);
            cnt += __shfl_down_sync(0xffffffff, cnt, o);
        }
        __shared__ float rs[MTHREADS / 32];
        __shared__ int   rc[MTHREADS / 32];
        if (lane == 0){ rs[w] = s; rc[w] = cnt; }
        __syncthreads();
        if (threadIdx.x == 0){
            float total = 0.f; int ctotal = 0;
            #pragma unroll
            for (int i = 0; i < MTHREADS / 32; i++){ total += rs[i]; ctotal += rc[i]; }
            // loss = beta*mean + mean = 1.25 * sum / n_z
            out[n_z]     = 1.25f * total / (float)n_z;
            out[n_z + 1] = (float)ctotal;
            __threadfence();
            g_ticket = 0;                       // reset for next graph replay
        }
    }
}

extern "C" void kernel_launch(void* const* d_in, const int* in_sizes, int n_in,
                              void* d_out, int out_size)
{
    const float* z   = (const float*)d_in[0];
    const float* emb = (const float*)d_in[1];
    float* out = (float*)d_out;

    const int chunks = (NVEC / QPT) / THREADS;   // 512
    vq_search<<<chunks * 2, THREADS>>>(z, emb);  // 1024 CTAs (x2 codebook halves)

    const int mblocks = NVEC / MTHREADS;         // 1024
    vq_merge<<<mblocks, MTHREADS>>>(emb, out, mblocks);
}